// round 3
// baseline (speedup 1.0000x reference)
#include <cuda_runtime.h>
#include <cstdint>

// ----------------------------------------------------------------------------
// Problem dims (fixed by dataset)
// ----------------------------------------------------------------------------
#define MDIM 8192   // B*S rows
#define NDIM 4096   // reduction dim
#define KDIM 4096   // output features
#define NGROUPS 32

// GEMM tiling
#define TILE_M  128          // CTA rows
#define TILE_KO 256          // CTA output features
#define CHUNK   32           // reduction elems per stage
#define STAGES  4
#define NCHUNK  (NDIM / CHUNK)   // 128

// Smem: rows of 32 floats (no pad); 16B-granule XOR swizzle by row parity.
#define SA_FLOATS (TILE_M  * CHUNK)            // 4096
#define SB_FLOATS (TILE_KO * CHUNK)            // 8192
#define STAGE_FLOATS (SA_FLOATS + SB_FLOATS)   // 12288
#define SMEM_BYTES (STAGES * STAGE_FLOATS * 4) // 196608

// Word offset (in floats) within a 32-float row, swizzled so that the two
// row parities occupy complementary bank halves. off must be a multiple of 4.
#define SWZ(row, off) ((off) ^ (((row) & 1) << 4))

// ----------------------------------------------------------------------------
// Device scratch (allocation-free rule: __device__ globals)
// Both stored PERMUTED: within each 32-k chunk, float at position w*4+j
// corresponds to original k = chunk*32 + w + 8*j  (w=k%8, j=k/8).
// So one float4 = the 4 k-step values an MMA lane needs for one chunk.
// ----------------------------------------------------------------------------
__device__ float g_Wdeq[(size_t)KDIM * NDIM];   // 64 MB dequant W, tf32-RN, permuted
__device__ float g_Xr[(size_t)MDIM * NDIM];     // 134 MB X, tf32-RN, permuted

// ----------------------------------------------------------------------------
// Helpers
// ----------------------------------------------------------------------------
__device__ __forceinline__ uint32_t smem_u32(const void* p) {
    uint32_t a;
    asm("{ .reg .u64 t; cvta.to.shared.u64 t, %1; cvt.u32.u64 %0, t; }"
        : "=r"(a) : "l"(p));
    return a;
}

__device__ __forceinline__ float rna_tf32(float x) {
    uint32_t u;
    asm("cvt.rna.tf32.f32 %0, %1;" : "=r"(u) : "f"(x));
    return __uint_as_float(u);
}

__device__ __forceinline__ void cp_async16(uint32_t sdst, const void* gsrc) {
    asm volatile("cp.async.cg.shared.global [%0], [%1], 16;"
                 :: "r"(sdst), "l"(gsrc) : "memory");
}

__device__ __forceinline__ void mma_tf32(float* d,
                                         uint32_t a0, uint32_t a1,
                                         uint32_t a2, uint32_t a3,
                                         uint32_t b0, uint32_t b1) {
    asm volatile(
        "mma.sync.aligned.m16n8k8.row.col.f32.tf32.tf32.f32 "
        "{%0,%1,%2,%3}, {%4,%5,%6,%7}, {%8,%9}, {%0,%1,%2,%3};"
        : "+f"(d[0]), "+f"(d[1]), "+f"(d[2]), "+f"(d[3])
        : "r"(a0), "r"(a1), "r"(a2), "r"(a3), "r"(b0), "r"(b1));
}

// ----------------------------------------------------------------------------
// Kernel 1: dequantize W (scales/zeros/mu2/mu1 fused), tf32-RN, permuted store
// ----------------------------------------------------------------------------
__global__ void dequant_kernel(const int* __restrict__ Wq,
                               const float* __restrict__ scales,
                               const float* __restrict__ zeros,
                               const float* __restrict__ mu1,
                               const float* __restrict__ mu2) {
    int k = blockIdx.x;
    float m2 = mu2[k];
    const int* wrow = Wq + (size_t)k * NDIM;
    float4* drow = reinterpret_cast<float4*>(g_Wdeq + (size_t)k * NDIM);
    for (int id = threadIdx.x; id < NDIM / 4; id += blockDim.x) {
        int chunk = id >> 3;   // 32-float chunk
        int w = id & 7;        // word-of-4 within chunk
        int g = chunk >> 2;    // quant group (= chunk*32/128)
        float s = scales[k * NGROUPS + g] * m2;
        float z = zeros[k * NGROUPS + g];
        float o[4];
        #pragma unroll
        for (int j = 0; j < 4; j++) {
            int n = chunk * 32 + w + 8 * j;
            o[j] = rna_tf32(((float)wrow[n] - z) * s * mu1[n]);
        }
        drow[id] = make_float4(o[0], o[1], o[2], o[3]);
    }
}

// ----------------------------------------------------------------------------
// Kernel 2: X -> tf32-RN, permuted store
// ----------------------------------------------------------------------------
__global__ void xprep_kernel(const float* __restrict__ x) {
    size_t row = blockIdx.x;
    const float* xr = x + row * NDIM;
    float4* dr = reinterpret_cast<float4*>(g_Xr + row * NDIM);
    for (int id = threadIdx.x; id < NDIM / 4; id += blockDim.x) {
        int chunk = id >> 3;
        int w = id & 7;
        float o[4];
        #pragma unroll
        for (int j = 0; j < 4; j++)
            o[j] = rna_tf32(xr[chunk * 32 + w + 8 * j]);
        dr[id] = make_float4(o[0], o[1], o[2], o[3]);
    }
}

// ----------------------------------------------------------------------------
// Kernel 3: tf32 mma.sync GEMM. out[m,k] = sum_n X[m,n]*Wdeq[k,n] + bias[k]
// CTA 128x256, 8 warps (2 M x 4 Kout), warp tile 64x64, 4-stage cp.async.
// Fragments: one float4 per (row, k mod 8 class) covers all 4 k-steps.
// ----------------------------------------------------------------------------
__global__ void __launch_bounds__(256, 1)
gemm_kernel(const float* __restrict__ bias, float* __restrict__ out) {
    extern __shared__ float smem[];

    const int tid = threadIdx.x;
    const int wid = tid >> 5;
    const int lane = tid & 31;
    const int g = lane >> 2;      // 0..7
    const int c = lane & 3;       // 0..3
    const int wm = wid & 1;       // warp row 0..1
    const int wn = wid >> 1;      // warp col 0..3

    const int k0 = blockIdx.x * TILE_KO;
    const int m0 = blockIdx.y * TILE_M;

    float acc[4][8][4];
    #pragma unroll
    for (int mi = 0; mi < 4; mi++)
        #pragma unroll
        for (int ni = 0; ni < 8; ni++)
            #pragma unroll
            for (int r = 0; r < 4; r++) acc[mi][ni][r] = 0.f;

    const uint32_t smem_base = smem_u32(smem);

    // ---- async copy of one chunk into stage buf ----
    auto issue = [&](int chunk, int buf) {
        const size_t n0 = (size_t)chunk * CHUNK;
        const uint32_t sA = smem_base + buf * STAGE_FLOATS * 4;
        const uint32_t sB = sA + SA_FLOATS * 4;
        #pragma unroll
        for (int i = 0; i < 4; i++) {            // A: 128 rows x 8 float4
            int id = tid + i * 256;
            int row = id >> 3, cc = id & 7;
            cp_async16(sA + (row * 32 + SWZ(row, cc * 4)) * 4,
                       g_Xr + (size_t)(m0 + row) * NDIM + n0 + cc * 4);
        }
        #pragma unroll
        for (int i = 0; i < 8; i++) {            // B: 256 rows x 8 float4
            int id = tid + i * 256;
            int row = id >> 3, cc = id & 7;
            cp_async16(sB + (row * 32 + SWZ(row, cc * 4)) * 4,
                       g_Wdeq + (size_t)(k0 + row) * NDIM + n0 + cc * 4);
        }
        asm volatile("cp.async.commit_group;" ::: "memory");
    };

    // ---- compute one chunk (4 MMA k-steps, fragments preloaded as float4) ----
    auto compute = [&](int buf) {
        const float* sA = smem + buf * STAGE_FLOATS + (wm * 64) * 32;
        const float* sB = smem + buf * STAGE_FLOATS + SA_FLOATS + (wn * 64) * 32;

        // A fragments: [mi][row-half][c-pair] -> float4 over ks=0..3
        float fA[4][2][2][4];
        #pragma unroll
        for (int mi = 0; mi < 4; mi++)
            #pragma unroll
            for (int rh = 0; rh < 2; rh++)
                #pragma unroll
                for (int cp = 0; cp < 2; cp++) {
                    int row = mi * 16 + rh * 8 + g;
                    int off = SWZ(row, (c + cp * 4) * 4);
                    *reinterpret_cast<float4*>(&fA[mi][rh][cp][0]) =
                        *reinterpret_cast<const float4*>(sA + row * 32 + off);
                }

        #pragma unroll
        for (int h = 0; h < 2; h++) {   // two ni-halves to bound registers
            float fB[4][2][4];
            #pragma unroll
            for (int nj = 0; nj < 4; nj++)
                #pragma unroll
                for (int cp = 0; cp < 2; cp++) {
                    int row = h * 32 + nj * 8 + g;
                    int off = SWZ(row, (c + cp * 4) * 4);
                    *reinterpret_cast<float4*>(&fB[nj][cp][0]) =
                        *reinterpret_cast<const float4*>(sB + row * 32 + off);
                }
            #pragma unroll
            for (int ks = 0; ks < 4; ks++)
                #pragma unroll
                for (int mi = 0; mi < 4; mi++)
                    #pragma unroll
                    for (int nj = 0; nj < 4; nj++)
                        mma_tf32(acc[mi][h * 4 + nj],
                                 __float_as_uint(fA[mi][0][0][ks]),
                                 __float_as_uint(fA[mi][1][0][ks]),
                                 __float_as_uint(fA[mi][0][1][ks]),
                                 __float_as_uint(fA[mi][1][1][ks]),
                                 __float_as_uint(fB[nj][0][ks]),
                                 __float_as_uint(fB[nj][1][ks]));
        }
    };

    // ---- pipeline: 4 stages, 1 sync per chunk ----
    issue(0, 0);
    issue(1, 1);
    issue(2, 2);
    for (int i = 0; i < NCHUNK; i++) {
        if (i < NCHUNK - 2)
            asm volatile("cp.async.wait_group 2;" ::: "memory");
        else
            asm volatile("cp.async.wait_group 0;" ::: "memory");
        __syncthreads();
        if (i + 3 < NCHUNK) issue(i + 3, (i + 3) & 3);
        compute(i & 3);
    }

    // ---- epilogue: bias + float2 stores ----
    #pragma unroll
    for (int ni = 0; ni < 8; ni++) {
        const int col = k0 + wn * 64 + ni * 8 + 2 * c;
        const float2 bv = *reinterpret_cast<const float2*>(bias + col);
        #pragma unroll
        for (int mi = 0; mi < 4; mi++) {
            const int row0 = m0 + wm * 64 + mi * 16 + g;
            float2 v0, v1;
            v0.x = acc[mi][ni][0] + bv.x;  v0.y = acc[mi][ni][1] + bv.y;
            v1.x = acc[mi][ni][2] + bv.x;  v1.y = acc[mi][ni][3] + bv.y;
            *reinterpret_cast<float2*>(out + (size_t)row0 * KDIM + col) = v0;
            *reinterpret_cast<float2*>(out + (size_t)(row0 + 8) * KDIM + col) = v1;
        }
    }
}

// ----------------------------------------------------------------------------
// Host launch
// ----------------------------------------------------------------------------
extern "C" void kernel_launch(void* const* d_in, const int* in_sizes, int n_in,
                              void* d_out, int out_size) {
    const float* x      = (const float*)d_in[0];
    const int*   Wq     = (const int*)d_in[1];
    const float* scales = (const float*)d_in[2];
    const float* zeros  = (const float*)d_in[3];
    const float* mu1    = (const float*)d_in[4];
    const float* mu2    = (const float*)d_in[5];
    const float* bias   = (const float*)d_in[6];
    float* out = (float*)d_out;

    dequant_kernel<<<KDIM, 256>>>(Wq, scales, zeros, mu1, mu2);
    xprep_kernel<<<MDIM, 256>>>(x);

    cudaFuncSetAttribute(gemm_kernel,
                         cudaFuncAttributeMaxDynamicSharedMemorySize,
                         SMEM_BYTES);
    dim3 grid(KDIM / TILE_KO, MDIM / TILE_M);   // (16, 64)
    gemm_kernel<<<grid, 256, SMEM_BYTES>>>(bias, out);
}

// round 4
// speedup vs baseline: 1.0125x; 1.0125x over previous
#include <cuda_runtime.h>
#include <cstdint>

// ----------------------------------------------------------------------------
// Problem dims (fixed by dataset)
// ----------------------------------------------------------------------------
#define MDIM 8192   // B*S rows
#define NDIM 4096   // reduction dim
#define KDIM 4096   // output features
#define NGROUPS 32

// GEMM tiling
#define TILE_M  128          // CTA rows
#define TILE_KO 256          // CTA output features
#define THREADS 512          // 16 warps: 2 (wm) x 8 (wn), warp tile 64x32
#define CHUNK   32           // reduction elems per stage
#define STAGES  4
#define NCHUNK  (NDIM / CHUNK)   // 128

// Smem: rows of 32 floats; 16B-granule XOR swizzle by row parity.
#define SA_FLOATS (TILE_M  * CHUNK)            // 4096
#define SB_FLOATS (TILE_KO * CHUNK)            // 8192
#define STAGE_FLOATS (SA_FLOATS + SB_FLOATS)   // 12288
#define SMEM_BYTES (STAGES * STAGE_FLOATS * 4) // 196608

// Word offset (floats) within a 32-float row; off must be a multiple of 4.
#define SWZ(row, off) ((off) ^ (((row) & 1) << 4))

// ----------------------------------------------------------------------------
// Device scratch. Both stored PERMUTED: within each 32-k chunk, float at
// position w*4+j corresponds to original k = chunk*32 + w + 8*j.
// One float4 = the 4 k-step values an MMA lane needs for one chunk.
// ----------------------------------------------------------------------------
__device__ float g_Wdeq[(size_t)KDIM * NDIM];   // 64 MB W, tf32-RN, permuted
__device__ float g_Xr[(size_t)MDIM * NDIM];     // 134 MB X, tf32-RN, permuted

// ----------------------------------------------------------------------------
// Helpers
// ----------------------------------------------------------------------------
__device__ __forceinline__ uint32_t smem_u32(const void* p) {
    uint32_t a;
    asm("{ .reg .u64 t; cvta.to.shared.u64 t, %1; cvt.u32.u64 %0, t; }"
        : "=r"(a) : "l"(p));
    return a;
}

__device__ __forceinline__ float rna_tf32(float x) {
    uint32_t u;
    asm("cvt.rna.tf32.f32 %0, %1;" : "=r"(u) : "f"(x));
    return __uint_as_float(u);
}

__device__ __forceinline__ void cp_async16(uint32_t sdst, const void* gsrc) {
    asm volatile("cp.async.cg.shared.global [%0], [%1], 16;"
                 :: "r"(sdst), "l"(gsrc) : "memory");
}

__device__ __forceinline__ void mma_tf32(float* d,
                                         float a0, float a1, float a2, float a3,
                                         float b0, float b1) {
    asm volatile(
        "mma.sync.aligned.m16n8k8.row.col.f32.tf32.tf32.f32 "
        "{%0,%1,%2,%3}, {%4,%5,%6,%7}, {%8,%9}, {%0,%1,%2,%3};"
        : "+f"(d[0]), "+f"(d[1]), "+f"(d[2]), "+f"(d[3])
        : "r"(__float_as_uint(a0)), "r"(__float_as_uint(a1)),
          "r"(__float_as_uint(a2)), "r"(__float_as_uint(a3)),
          "r"(__float_as_uint(b0)), "r"(__float_as_uint(b1)));
}

// ----------------------------------------------------------------------------
// Kernel 1: dequantize W (scales/zeros/mu2/mu1 fused), tf32-RN, permuted
// ----------------------------------------------------------------------------
__global__ void dequant_kernel(const int* __restrict__ Wq,
                               const float* __restrict__ scales,
                               const float* __restrict__ zeros,
                               const float* __restrict__ mu1,
                               const float* __restrict__ mu2) {
    int k = blockIdx.x;
    float m2 = mu2[k];
    const int* wrow = Wq + (size_t)k * NDIM;
    float4* drow = reinterpret_cast<float4*>(g_Wdeq + (size_t)k * NDIM);
    for (int id = threadIdx.x; id < NDIM / 4; id += blockDim.x) {
        int chunk = id >> 3;   // 32-float chunk
        int w = id & 7;        // word-of-4 within chunk
        int g = chunk >> 2;    // quant group
        float s = scales[k * NGROUPS + g] * m2;
        float z = zeros[k * NGROUPS + g];
        float o[4];
        #pragma unroll
        for (int j = 0; j < 4; j++) {
            int n = chunk * 32 + w + 8 * j;
            o[j] = rna_tf32(((float)wrow[n] - z) * s * mu1[n]);
        }
        drow[id] = make_float4(o[0], o[1], o[2], o[3]);
    }
}

// ----------------------------------------------------------------------------
// Kernel 2: X -> tf32-RN, permuted
// ----------------------------------------------------------------------------
__global__ void xprep_kernel(const float* __restrict__ x) {
    size_t row = blockIdx.x;
    const float* xr = x + row * NDIM;
    float4* dr = reinterpret_cast<float4*>(g_Xr + row * NDIM);
    for (int id = threadIdx.x; id < NDIM / 4; id += blockDim.x) {
        int chunk = id >> 3;
        int w = id & 7;
        float o[4];
        #pragma unroll
        for (int j = 0; j < 4; j++)
            o[j] = rna_tf32(xr[chunk * 32 + w + 8 * j]);
        dr[id] = make_float4(o[0], o[1], o[2], o[3]);
    }
}

// ----------------------------------------------------------------------------
// Kernel 3: tf32 mma.sync GEMM. out[m,k] = sum_n X[m,n]*Wdeq[k,n] + bias[k]
// CTA 128x256, 16 warps (2 wm x 8 wn), warp tile 64x32, 4-stage cp.async.
// ----------------------------------------------------------------------------
__global__ void __launch_bounds__(THREADS, 1)
gemm_kernel(const float* __restrict__ bias, float* __restrict__ out) {
    extern __shared__ float smem[];

    const int tid = threadIdx.x;
    const int wid = tid >> 5;
    const int lane = tid & 31;
    const int g = lane >> 2;      // 0..7
    const int c = lane & 3;       // 0..3
    const int wm = wid & 1;       // warp row 0..1 (64 rows each)
    const int wn = wid >> 1;      // warp col 0..7 (32 cols each)

    const int k0 = blockIdx.x * TILE_KO;
    const int m0 = blockIdx.y * TILE_M;

    float acc[4][4][4];           // [mi][nj][frag]
    #pragma unroll
    for (int mi = 0; mi < 4; mi++)
        #pragma unroll
        for (int nj = 0; nj < 4; nj++)
            #pragma unroll
            for (int r = 0; r < 4; r++) acc[mi][nj][r] = 0.f;

    const uint32_t smem_base = smem_u32(smem);

    // ---- async copy of one chunk into stage buf ----
    auto issue = [&](int chunk, int buf) {
        const size_t n0 = (size_t)chunk * CHUNK;
        const uint32_t sA = smem_base + buf * STAGE_FLOATS * 4;
        const uint32_t sB = sA + SA_FLOATS * 4;
        #pragma unroll
        for (int i = 0; i < 2; i++) {            // A: 128 rows x 8 float4
            int id = tid + i * THREADS;
            int row = id >> 3, cc = id & 7;
            cp_async16(sA + (row * 32 + SWZ(row, cc * 4)) * 4,
                       g_Xr + (size_t)(m0 + row) * NDIM + n0 + cc * 4);
        }
        #pragma unroll
        for (int i = 0; i < 4; i++) {            // B: 256 rows x 8 float4
            int id = tid + i * THREADS;
            int row = id >> 3, cc = id & 7;
            cp_async16(sB + (row * 32 + SWZ(row, cc * 4)) * 4,
                       g_Wdeq + (size_t)(k0 + row) * NDIM + n0 + cc * 4);
        }
        asm volatile("cp.async.commit_group;" ::: "memory");
    };

    // ---- compute one chunk (4 k-steps). fB whole, fA per mi. ----
    auto compute = [&](int buf) {
        const float* sA = smem + buf * STAGE_FLOATS + (wm * 64) * 32;
        const float* sB = smem + buf * STAGE_FLOATS + SA_FLOATS + (wn * 32) * 32;

        float fB[4][2][4];        // [nj][cp][ks]
        #pragma unroll
        for (int nj = 0; nj < 4; nj++)
            #pragma unroll
            for (int cp = 0; cp < 2; cp++) {
                int row = nj * 8 + g;
                int off = SWZ(row, (c + cp * 4) * 4);
                *reinterpret_cast<float4*>(&fB[nj][cp][0]) =
                    *reinterpret_cast<const float4*>(sB + row * 32 + off);
            }

        #pragma unroll
        for (int mi = 0; mi < 4; mi++) {
            float fA[2][2][4];    // [rh][cp][ks]
            #pragma unroll
            for (int rh = 0; rh < 2; rh++)
                #pragma unroll
                for (int cp = 0; cp < 2; cp++) {
                    int row = mi * 16 + rh * 8 + g;
                    int off = SWZ(row, (c + cp * 4) * 4);
                    *reinterpret_cast<float4*>(&fA[rh][cp][0]) =
                        *reinterpret_cast<const float4*>(sA + row * 32 + off);
                }
            #pragma unroll
            for (int ks = 0; ks < 4; ks++)
                #pragma unroll
                for (int nj = 0; nj < 4; nj++)
                    mma_tf32(acc[mi][nj],
                             fA[0][0][ks], fA[1][0][ks],
                             fA[0][1][ks], fA[1][1][ks],
                             fB[nj][0][ks], fB[nj][1][ks]);
        }
    };

    // ---- pipeline: 4 stages, 1 sync per chunk ----
    issue(0, 0);
    issue(1, 1);
    issue(2, 2);
    for (int i = 0; i < NCHUNK; i++) {
        if (i < NCHUNK - 2)
            asm volatile("cp.async.wait_group 2;" ::: "memory");
        else
            asm volatile("cp.async.wait_group 0;" ::: "memory");
        __syncthreads();
        if (i + 3 < NCHUNK) issue(i + 3, (i + 3) & 3);
        compute(i & 3);
    }

    // ---- epilogue: bias + float2 stores ----
    #pragma unroll
    for (int nj = 0; nj < 4; nj++) {
        const int col = k0 + wn * 32 + nj * 8 + 2 * c;
        const float2 bv = *reinterpret_cast<const float2*>(bias + col);
        #pragma unroll
        for (int mi = 0; mi < 4; mi++) {
            const int row0 = m0 + wm * 64 + mi * 16 + g;
            float2 v0, v1;
            v0.x = acc[mi][nj][0] + bv.x;  v0.y = acc[mi][nj][1] + bv.y;
            v1.x = acc[mi][nj][2] + bv.x;  v1.y = acc[mi][nj][3] + bv.y;
            *reinterpret_cast<float2*>(out + (size_t)row0 * KDIM + col) = v0;
            *reinterpret_cast<float2*>(out + (size_t)(row0 + 8) * KDIM + col) = v1;
        }
    }
}

// ----------------------------------------------------------------------------
// Host launch
// ----------------------------------------------------------------------------
extern "C" void kernel_launch(void* const* d_in, const int* in_sizes, int n_in,
                              void* d_out, int out_size) {
    const float* x      = (const float*)d_in[0];
    const int*   Wq     = (const int*)d_in[1];
    const float* scales = (const float*)d_in[2];
    const float* zeros  = (const float*)d_in[3];
    const float* mu1    = (const float*)d_in[4];
    const float* mu2    = (const float*)d_in[5];
    const float* bias   = (const float*)d_in[6];
    float* out = (float*)d_out;

    dequant_kernel<<<KDIM, 256>>>(Wq, scales, zeros, mu1, mu2);
    xprep_kernel<<<MDIM, 256>>>(x);

    cudaFuncSetAttribute(gemm_kernel,
                         cudaFuncAttributeMaxDynamicSharedMemorySize,
                         SMEM_BYTES);
    dim3 grid(KDIM / TILE_KO, MDIM / TILE_M);   // (16, 64)
    gemm_kernel<<<grid, THREADS, SMEM_BYTES>>>(bias, out);
}